// round 9
// baseline (speedup 1.0000x reference)
#include <cuda_runtime.h>
#include <cuda_bf16.h>
#include <cuda_fp16.h>
#include <math.h>

// Fixed shapes: seq (256,40) int32, sim (512,512) f32, pers (512,512,512) f32,
// weights (2,) f32, output scalar f32.
constexpr int V = 512;
constexpr int B = 256;
constexpr int L = 40;
constexpr int ROWS = B * (L - 1);        // 9984
constexpr int WARPS_PER_BLOCK = 4;       // 128 threads, 1 row per warp
constexpr int NBLOCKS = ROWS / WARPS_PER_BLOCK;  // 2496

constexpr float LOG2E = 1.44269504088896340736f;
constexpr float LN2   = 0.69314718055994530942f;

// 32-byte global load with L2 evict_last (sm_103a ptxas requires .v8.b32).
struct F8 { float v[8]; };
__device__ __forceinline__ F8 ldg_el8(const float* p) {
    F8 r;
    asm("ld.global.nc.L2::evict_last.v8.b32 {%0,%1,%2,%3,%4,%5,%6,%7}, [%8];"
        : "=f"(r.v[0]), "=f"(r.v[1]), "=f"(r.v[2]), "=f"(r.v[3]),
          "=f"(r.v[4]), "=f"(r.v[5]), "=f"(r.v[6]), "=f"(r.v[7])
        : "l"(p));
    return r;
}

__global__ void init_out_kernel(float* out) {
    out[0] = (float)B * logf((float)V);  // nll0
}

__global__ __launch_bounds__(128)
void nll_kernel(const int* __restrict__ seq,
                const float* __restrict__ sim,
                const float* __restrict__ pers,
                const float* __restrict__ w,
                float* __restrict__ out) {
    const int warp = threadIdx.x >> 5;
    const int lane = threadIdx.x & 31;
    const int row  = blockIdx.x * WARPS_PER_BLOCK + warp;   // 0..ROWS-1
    const int b = row / (L - 1);
    const int t = row % (L - 1);
    const int base = b * L + t;

    const int prev = seq[base];
    const int tgt  = seq[base + 1];
    // fold log2(e) into the weights: y = log2(e) * (w0*s + w1*p)
    const float w0l = w[0] * LOG2E;
    const float w1l = w[1] * LOG2E;

    // Each lane owns elements (lane + 32*j)*8 + c, j in {0,1}, c in [0,8).
    const float* srow = sim + (size_t)prev * V;
    F8 sv[2];
    #pragma unroll
    for (int j = 0; j < 2; j++) sv[j] = ldg_el8(srow + (lane + 32 * j) * 8);

    F8 pv[2];
    if (t >= 1) {
        const int p0 = seq[base - 1];
        const float* prow = pers + ((size_t)p0 * V + (size_t)prev) * V;
        #pragma unroll
        for (int j = 0; j < 2; j++) pv[j] = ldg_el8(prow + (lane + 32 * j) * 8);
    } else {
        #pragma unroll
        for (int j = 0; j < 2; j++)
            #pragma unroll
            for (int c = 0; c < 8; c++) pv[j].v[c] = 0.f;
    }

    const int tj = tgt >> 8;            // which 32-lane chunk
    const int tl = (tgt >> 3) & 31;     // owning lane
    const int tc = tgt & 7;             // component within F8

    // ---- sum of 2^y via packed f16x2 ex2 ----
    float se = 0.f;     // f32 accumulator
    float tv = 0.f;     // target y (log2 domain)
    #pragma unroll
    for (int j = 0; j < 2; j++) {
        float y[8];
        #pragma unroll
        for (int c = 0; c < 8; c++)
            y[c] = fmaf(w1l, pv[j].v[c], w0l * sv[j].v[c]);

        #pragma unroll
        for (int c = 0; c < 8; c += 4) {
            __half2 ea = h2exp2(__floats2half2_rn(y[c],     y[c + 1]));
            __half2 eb = h2exp2(__floats2half2_rn(y[c + 2], y[c + 3]));
            __half2 hs = __hadd2(ea, eb);
            float2 f = __half22float2(hs);
            se += f.x + f.y;
        }
        if (j == tj) tv = y[tc];
    }

    #pragma unroll
    for (int o = 16; o; o >>= 1) se += __shfl_xor_sync(0xffffffffu, se, o);
    tv = __shfl_sync(0xffffffffu, tv, tl);

    // nll = ln2 * (log2(sum 2^y) - y_tgt)
    __shared__ float sh[WARPS_PER_BLOCK];
    if (lane == 0) sh[warp] = LN2 * (__log2f(se) - tv);
    __syncthreads();

    if (threadIdx.x == 0) {
        float acc = 0.f;
        #pragma unroll
        for (int i = 0; i < WARPS_PER_BLOCK; i++) acc += sh[i];
        atomicAdd(out, acc);
    }
}

extern "C" void kernel_launch(void* const* d_in, const int* in_sizes, int n_in,
                              void* d_out, int out_size) {
    const int*   seq  = (const int*)  d_in[0];
    const float* sim  = (const float*)d_in[1];
    const float* pers = (const float*)d_in[2];
    const float* w    = (const float*)d_in[3];
    float* out = (float*)d_out;

    init_out_kernel<<<1, 1>>>(out);
    nll_kernel<<<NBLOCKS, 128>>>(seq, sim, pers, w, out);
}

// round 10
// speedup vs baseline: 1.0683x; 1.0683x over previous
#include <cuda_runtime.h>
#include <cuda_bf16.h>
#include <cuda_fp16.h>
#include <math.h>

// Fixed shapes: seq (256,40) int32, sim (512,512) f32, pers (512,512,512) f32,
// weights (2,) f32, output scalar f32.
constexpr int V = 512;
constexpr int B = 256;
constexpr int L = 40;
constexpr int ROWS = B * (L - 1);        // 9984
constexpr int WARPS_PER_BLOCK = 8;       // 256 threads, 1 row per warp
constexpr int NBLOCKS = ROWS / WARPS_PER_BLOCK;  // 1248

constexpr float LOG2E = 1.44269504088896340736f;
constexpr float LN2   = 0.69314718055994530942f;

// 32-byte global load with L2 evict_last (sm_103a ptxas requires .v8.b32).
struct F8 { float v[8]; };
__device__ __forceinline__ F8 ldg_el8(const float* p) {
    F8 r;
    asm("ld.global.nc.L2::evict_last.v8.b32 {%0,%1,%2,%3,%4,%5,%6,%7}, [%8];"
        : "=f"(r.v[0]), "=f"(r.v[1]), "=f"(r.v[2]), "=f"(r.v[3]),
          "=f"(r.v[4]), "=f"(r.v[5]), "=f"(r.v[6]), "=f"(r.v[7])
        : "l"(p));
    return r;
}

__global__ void init_out_kernel(float* out) {
    out[0] = (float)B * logf((float)V);  // nll0
}

__global__ __launch_bounds__(256)
void nll_kernel(const int* __restrict__ seq,
                const float* __restrict__ sim,
                const float* __restrict__ pers,
                const float* __restrict__ w,
                float* __restrict__ out) {
    const int warp = threadIdx.x >> 5;
    const int lane = threadIdx.x & 31;
    const int row  = blockIdx.x * WARPS_PER_BLOCK + warp;   // 0..ROWS-1
    const int b = row / (L - 1);
    const int t = row % (L - 1);
    const int base = b * L + t;

    const int prev = seq[base];
    const int tgt  = seq[base + 1];
    // fold log2(e) into the weights: y = log2(e) * (w0*s + w1*p)
    const float w0l = w[0] * LOG2E;
    const float w1l = w[1] * LOG2E;

    // ---- DRAM stream first: 2x v8 (64 B) per lane from the random pers row ----
    // t==0 rows (256 of 9984) read a clamped valid row with weight 0 (branchless).
    const bool hasP = (t >= 1);
    const int  p0   = hasP ? seq[base - 1] : prev;
    const float w1r = hasP ? w1l : 0.f;
    const float* prow = pers + ((size_t)p0 * V + (size_t)prev) * V;
    F8 pv[2];
    #pragma unroll
    for (int j = 0; j < 2; j++) pv[j] = ldg_el8(prow + (lane + 32 * j) * 8);

    // ---- L2-resident sim row ----
    const float* srow = sim + (size_t)prev * V;
    F8 sv[2];
    #pragma unroll
    for (int j = 0; j < 2; j++) sv[j] = ldg_el8(srow + (lane + 32 * j) * 8);

    const int tj = tgt >> 8;            // which 32-lane chunk
    const int tl = (tgt >> 3) & 31;     // owning lane
    const int tc = tgt & 7;             // component within F8

    // ---- sum of 2^y via packed f16x2 ex2 ----
    float se = 0.f;     // f32 accumulator
    float tv = 0.f;     // target y (log2 domain)
    #pragma unroll
    for (int j = 0; j < 2; j++) {
        float y[8];
        #pragma unroll
        for (int c = 0; c < 8; c++)
            y[c] = fmaf(w1r, pv[j].v[c], w0l * sv[j].v[c]);

        #pragma unroll
        for (int c = 0; c < 8; c += 4) {
            __half2 ea = h2exp2(__floats2half2_rn(y[c],     y[c + 1]));
            __half2 eb = h2exp2(__floats2half2_rn(y[c + 2], y[c + 3]));
            __half2 hs = __hadd2(ea, eb);
            float2 f = __half22float2(hs);
            se += f.x + f.y;
        }
        if (j == tj) tv = y[tc];
    }

    #pragma unroll
    for (int o = 16; o; o >>= 1) se += __shfl_xor_sync(0xffffffffu, se, o);
    tv = __shfl_sync(0xffffffffu, tv, tl);

    // nll = ln2 * (log2(sum 2^y) - y_tgt)
    __shared__ float sh[WARPS_PER_BLOCK];
    if (lane == 0) sh[warp] = LN2 * (__log2f(se) - tv);
    __syncthreads();

    if (threadIdx.x == 0) {
        float acc = 0.f;
        #pragma unroll
        for (int i = 0; i < WARPS_PER_BLOCK; i++) acc += sh[i];
        atomicAdd(out, acc);
    }
}

extern "C" void kernel_launch(void* const* d_in, const int* in_sizes, int n_in,
                              void* d_out, int out_size) {
    const int*   seq  = (const int*)  d_in[0];
    const float* sim  = (const float*)d_in[1];
    const float* pers = (const float*)d_in[2];
    const float* w    = (const float*)d_in[3];
    float* out = (float*)d_out;

    init_out_kernel<<<1, 1>>>(out);
    nll_kernel<<<NBLOCKS, 256>>>(seq, sim, pers, w, out);
}

// round 11
// speedup vs baseline: 1.2330x; 1.1541x over previous
#include <cuda_runtime.h>
#include <cuda_bf16.h>
#include <cuda_fp16.h>
#include <math.h>

// Fixed shapes: seq (256,40) int32, sim (512,512) f32, pers (512,512,512) f32,
// weights (2,) f32, output scalar f32.
constexpr int V = 512;
constexpr int B = 256;
constexpr int L = 40;
constexpr int ROWS = B * (L - 1);        // 9984
constexpr int WARPS_PER_BLOCK = 8;       // 256 threads, 1 row per warp
constexpr int NBLOCKS = ROWS / WARPS_PER_BLOCK;  // 1248

constexpr float LOG2E = 1.44269504088896340736f;
constexpr float LN2   = 0.69314718055994530942f;

// 32-byte global load with L2 evict_last (sm_103a ptxas requires .v8.b32).
struct F8 { float v[8]; };
__device__ __forceinline__ F8 ldg_el8(const float* p) {
    F8 r;
    asm("ld.global.nc.L2::evict_last.v8.b32 {%0,%1,%2,%3,%4,%5,%6,%7}, [%8];"
        : "=f"(r.v[0]), "=f"(r.v[1]), "=f"(r.v[2]), "=f"(r.v[3]),
          "=f"(r.v[4]), "=f"(r.v[5]), "=f"(r.v[6]), "=f"(r.v[7])
        : "l"(p));
    return r;
}

__global__ void init_out_kernel(float* out) {
    out[0] = (float)B * logf((float)V);  // nll0
    cudaTriggerProgrammaticLaunchCompletion();
}

__global__ __launch_bounds__(256)
void nll_kernel(const int* __restrict__ seq,
                const float* __restrict__ sim,
                const float* __restrict__ pers,
                const float* __restrict__ w,
                float* __restrict__ out) {
    const int warp = threadIdx.x >> 5;
    const int lane = threadIdx.x & 31;
    const int row  = blockIdx.x * WARPS_PER_BLOCK + warp;   // 0..ROWS-1
    const int b = row / (L - 1);
    const int t = row % (L - 1);
    const int base = b * L + t;

    const int prev = seq[base];
    const int tgt  = seq[base + 1];
    // fold log2(e) into the weights: y = log2(e) * (w0*s + w1*p)
    const float w0l = w[0] * LOG2E;
    const float w1l = w[1] * LOG2E;

    // ---- DRAM stream first: 2x v8 (64 B) per lane from the random pers row ----
    // t==0 rows (256 of 9984) read a clamped valid row with weight 0 (branchless).
    const bool hasP = (t >= 1);
    const int  p0   = hasP ? seq[base - 1] : prev;
    const float w1r = hasP ? w1l : 0.f;
    const float* prow = pers + ((size_t)p0 * V + (size_t)prev) * V;
    F8 pv[2];
    #pragma unroll
    for (int j = 0; j < 2; j++) pv[j] = ldg_el8(prow + (lane + 32 * j) * 8);

    // ---- L2-resident sim row ----
    const float* srow = sim + (size_t)prev * V;
    F8 sv[2];
    #pragma unroll
    for (int j = 0; j < 2; j++) sv[j] = ldg_el8(srow + (lane + 32 * j) * 8);

    const int tj = tgt >> 8;            // which 32-lane chunk
    const int tl = (tgt >> 3) & 31;     // owning lane
    const int tc = tgt & 7;             // component within F8

    // ---- sum of 2^y via packed f16x2 ex2 ----
    float se = 0.f;     // f32 accumulator
    float tv = 0.f;     // target y (log2 domain)
    #pragma unroll
    for (int j = 0; j < 2; j++) {
        float y[8];
        #pragma unroll
        for (int c = 0; c < 8; c++)
            y[c] = fmaf(w1r, pv[j].v[c], w0l * sv[j].v[c]);

        #pragma unroll
        for (int c = 0; c < 8; c += 4) {
            __half2 ea = h2exp2(__floats2half2_rn(y[c],     y[c + 1]));
            __half2 eb = h2exp2(__floats2half2_rn(y[c + 2], y[c + 3]));
            __half2 hs = __hadd2(ea, eb);
            float2 f = __half22float2(hs);
            se += f.x + f.y;
        }
        if (j == tj) tv = y[tc];
    }

    #pragma unroll
    for (int o = 16; o; o >>= 1) se += __shfl_xor_sync(0xffffffffu, se, o);
    tv = __shfl_sync(0xffffffffu, tv, tl);

    // nll = ln2 * (log2(sum 2^y) - y_tgt)
    __shared__ float sh[WARPS_PER_BLOCK];
    if (lane == 0) sh[warp] = LN2 * (__log2f(se) - tv);
    __syncthreads();

    if (threadIdx.x == 0) {
        float acc = 0.f;
        #pragma unroll
        for (int i = 0; i < WARPS_PER_BLOCK; i++) acc += sh[i];
        // PDL: make sure the init kernel's out[0] = nll0 store is visible
        // before accumulating into it. All the heavy work above overlapped
        // the init node and this kernel's launch latency.
        cudaGridDependencySynchronize();
        atomicAdd(out, acc);
    }
}

extern "C" void kernel_launch(void* const* d_in, const int* in_sizes, int n_in,
                              void* d_out, int out_size) {
    const int*   seq  = (const int*)  d_in[0];
    const float* sim  = (const float*)d_in[1];
    const float* pers = (const float*)d_in[2];
    const float* w    = (const float*)d_in[3];
    float* out = (float*)d_out;

    init_out_kernel<<<1, 1>>>(out);

    // Launch the main kernel with Programmatic Stream Serialization so it
    // starts while init_out_kernel is still in flight; the in-kernel
    // cudaGridDependencySynchronize() enforces the only real dependency.
    cudaLaunchConfig_t cfg = {};
    cfg.gridDim  = dim3(NBLOCKS, 1, 1);
    cfg.blockDim = dim3(256, 1, 1);
    cfg.dynamicSmemBytes = 0;
    cudaLaunchAttribute attrs[1];
    attrs[0].id = cudaLaunchAttributeProgrammaticStreamSerialization;
    attrs[0].val.programmaticStreamSerializationAllowed = 1;
    cfg.attrs = attrs;
    cfg.numAttrs = 1;
    cudaLaunchKernelEx(&cfg, nll_kernel, seq, sim, pers, w, out);
}